// round 3
// baseline (speedup 1.0000x reference)
#include <cuda_runtime.h>
#include <cuda_bf16.h>
#include <math.h>

// Problem constants (fixed by the reference)
#define BB 8
#define SS 4096
#define DD 1024
#define HH 16
#define HD 64
#define NR 32
#define NFREQ 32            // HD/2
#define ROWS (BB * SS * HH) // 524288

// Scratch (static device globals — no runtime allocation)
__device__ float g_cos_tab[SS * NFREQ]; // 512 KB
__device__ float g_sin_tab[SS * NFREQ]; // 512 KB
__device__ int   g_not_identity;

// ---------------------------------------------------------------------------
// Pre-kernel 1: reset identity flag
__global__ void k_flag_init() { g_not_identity = 0; }

// Pre-kernel 2: check r_matrix == I (4096 elems)
__global__ void k_check_identity(const float* __restrict__ rm) {
    int e = blockIdx.x * blockDim.x + threadIdx.x;
    if (e < HD * HD) {
        float expect = ((e / HD) == (e % HD)) ? 1.0f : 0.0f;
        if (rm[e] != expect) g_not_identity = 1; // benign race: all write 1
    }
}

// Pre-kernel 3: fill RoPE sin/cos table with accurate range reduction.
// angle = s * inv_freq[k]; reduce mod 2*pi in double, then float sincos.
__global__ void k_rope_table(const float* __restrict__ inv_freq) {
    int e = blockIdx.x * blockDim.x + threadIdx.x; // 0 .. S*NFREQ-1
    if (e >= SS * NFREQ) return;
    int s = e >> 5;
    int k = e & 31;
    double a  = (double)s * (double)inv_freq[k];
    const double TWO_PI = 6.283185307179586476925286766559;
    double r = a - floor(a / TWO_PI + 0.5) * TWO_PI; // r in [-pi, pi]
    float rf = (float)r;
    float sv, cv;
    sincosf(rf, &sv, &cv);
    g_sin_tab[e] = sv;
    g_cos_tab[e] = cv;
}

// ---------------------------------------------------------------------------
// Main kernel: 128 threads/block, each thread owns one 64-float row in shared.
// Block covers 128 contiguous rows = 8192 floats = 32 KB of x.
#define TPB 128
#define ROW_PITCH 65  // padded row stride in shared (bank-conflict-free)

__global__ void __launch_bounds__(TPB)
k_main(const float* __restrict__ x,
       const float* __restrict__ thetas,
       const float* __restrict__ r_pairs,
       const float* __restrict__ theta_scale,
       const float* __restrict__ r_matrix,
       float* __restrict__ out) {
    __shared__ float buf[TPB * ROW_PITCH];        // 33,280 B
    __shared__ float rot_c[NR], rot_s[NR];
    __shared__ int   rot_i[NR], rot_j[NR];
    __shared__ float cs_tab[8][33], sn_tab[8][33]; // 8 s-values per block, padded

    const int tid = threadIdx.x;
    const int bid = blockIdx.x;
    const long long elem_base = (long long)bid * (TPB * HD); // float index into x/out

    // --- rotation params (uniform across block) ---
    if (tid < NR) {
        int i = (int)r_pairs[2 * tid];
        int j = (int)r_pairs[2 * tid + 1];
        float t = thetas[tid] * theta_scale[0];
        float sv, cv;
        sincosf(t, &sv, &cv);
        rot_i[tid] = i; rot_j[tid] = j;
        rot_c[tid] = cv; rot_s[tid] = sv;
    }

    // --- stage input: coalesced float4 global -> padded shared rows ---
    const float4* __restrict__ xin = reinterpret_cast<const float4*>(x) + (elem_base >> 2);
    #pragma unroll
    for (int it = 0; it < 16; it++) {
        int g = tid + it * TPB;        // 0 .. 2047 (float4 index within block chunk)
        float4 v = xin[g];
        int row = g >> 4;              // 16 float4 per row
        int c4  = (g & 15) << 2;
        float* p = &buf[row * ROW_PITCH + c4];
        p[0] = v.x; p[1] = v.y; p[2] = v.z; p[3] = v.w;
    }

    // --- stage RoPE sin/cos for the 8 s-positions this block touches ---
    // global row = bid*128 + t ; s = (row >> 4) & (S-1); block spans s-group
    // indices (bid*8 .. bid*8+7) within one batch.
    {
        int sg0 = (bid * TPB) >> 4; // first (b*S+s) index
        for (int e = tid; e < 8 * NFREQ; e += TPB) {
            int l = e >> 5, k = e & 31;
            int s = (sg0 + l) & (SS - 1);
            cs_tab[l][k] = g_cos_tab[s * NFREQ + k];
            sn_tab[l][k] = g_sin_tab[s * NFREQ + k];
        }
    }
    __syncthreads();

    float* myrow = &buf[tid * ROW_PITCH];

    // --- 32 sequential Givens rotations (dynamic indices -> shared) ---
    for (int r = 0; r < NR; r++) {
        int i = rot_i[r], j = rot_j[r];
        float c = rot_c[r], s = rot_s[r];
        float xi = myrow[i];
        float xj = myrow[j];
        if (i == j) {
            myrow[i] = xi * c;
        } else {
            myrow[i] = fmaf(xj, s, xi * c);
            myrow[j] = fmaf(xj, c, -xi * s);
        }
    }

    // --- generic fallback: y = y @ r_matrix (skipped when identity) ---
    if (g_not_identity) {
        float yl[HD];
        #pragma unroll
        for (int k = 0; k < HD; k++) yl[k] = myrow[k];
        for (int c = 0; c < HD; c++) {
            float acc = 0.0f;
            #pragma unroll
            for (int k = 0; k < HD; k++)
                acc = fmaf(yl[k], __ldg(&r_matrix[k * HD + c]), acc);
            myrow[c] = acc;
        }
    }

    // --- RoPE (half-concat layout), in place ---
    {
        int l = tid >> 4; // which of the 8 s-values
        float hi[NFREQ];
        #pragma unroll
        for (int k = 0; k < NFREQ; k++) {
            float y0 = myrow[2 * k];
            float y1 = myrow[2 * k + 1];
            float c = cs_tab[l][k];
            float s = sn_tab[l][k];
            float lo = y0 * c - y1 * s;
            hi[k]    = fmaf(y0, s, y1 * c);
            myrow[k] = lo;           // safe: write pos k, future reads are >= 2(k+1)
        }
        #pragma unroll
        for (int k = 0; k < NFREQ; k++) myrow[NFREQ + k] = hi[k];
    }
    __syncthreads();

    // --- stage output: padded shared rows -> coalesced float4 global ---
    float4* __restrict__ op = reinterpret_cast<float4*>(out) + (elem_base >> 2);
    #pragma unroll
    for (int it = 0; it < 16; it++) {
        int g = tid + it * TPB;
        int row = g >> 4;
        int c4  = (g & 15) << 2;
        const float* p = &buf[row * ROW_PITCH + c4];
        op[g] = make_float4(p[0], p[1], p[2], p[3]);
    }
}

// ---------------------------------------------------------------------------
extern "C" void kernel_launch(void* const* d_in, const int* in_sizes, int n_in,
                              void* d_out, int out_size) {
    const float* x        = (const float*)d_in[0];
    const float* thetas   = (const float*)d_in[1];
    const float* r_pairs  = (const float*)d_in[2];
    const float* t_scale  = (const float*)d_in[3];
    // d_in[4] = n_rots_scale (unused by the reference)
    const float* r_matrix = (const float*)d_in[5];
    const float* inv_freq = (const float*)d_in[6];
    float* out = (float*)d_out;

    k_flag_init<<<1, 1>>>();
    k_check_identity<<<(HD * HD + 255) / 256, 256>>>(r_matrix);
    k_rope_table<<<(SS * NFREQ + 255) / 256, 256>>>(inv_freq);

    int nblocks = ROWS / TPB; // 4096
    k_main<<<nblocks, TPB>>>(x, thetas, r_pairs, t_scale, r_matrix, out);
}